// round 1
// baseline (speedup 1.0000x reference)
#include <cuda_runtime.h>
#include <cstdint>
#include <cstddef>

// Problem dims (fixed by the reference)
#define T_DIM 4096   // time frames (Tq == Tk)
#define Q_DIM 256    // query/key feature dim
#define H_DIM 256    // hidden dim
#define V_DIM 80     // value feature dim
#define NSHIFT 4
#define STEPSZ 2

// ---------------- scratch (allocation-free: __device__ globals) ----------------
__device__ float g_Qh[(size_t)T_DIM * H_DIM];       // 4 MB
__device__ float g_Kh[(size_t)T_DIM * H_DIM];       // 4 MB
__device__ float g_P[(size_t)T_DIM * T_DIM];        // 64 MB : S, then softmax(S) in place
__device__ float g_Pmix[(size_t)T_DIM * T_DIM];     // 64 MB : shift-mixed attention

// =======================================================================
// GEMM: C[m][n] = sum_k A[m][k] * B[n][k]   (A: MxK, B: NxK, C: MxN, row-major)
// 128x128 block tile, 8x8 thread tile, BK=16. M,N,K must be multiples of 128/128/16.
// =======================================================================
__global__ __launch_bounds__(256, 2)
void gemm_abt(const float* __restrict__ A, const float* __restrict__ B,
              float* __restrict__ C, int M, int N, int K) {
    __shared__ float As[16][132];   // k-major (transposed) + pad
    __shared__ float Bs[16][132];

    const int tid = threadIdx.x;
    const int bm = blockIdx.y * 128;
    const int bn = blockIdx.x * 128;
    const int ty = tid >> 4;        // 0..15 -> rows ty*8..ty*8+7
    const int tx = tid & 15;        // 0..15 -> cols tx*8..tx*8+7

    float acc[8][8];
#pragma unroll
    for (int i = 0; i < 8; i++)
#pragma unroll
        for (int j = 0; j < 8; j++) acc[i][j] = 0.f;

    const int lr = tid >> 2;        // 0..63 (row within tile, +64 for 2nd load)
    const int lg = tid & 3;         // k-group (4 floats each)

    for (int k0 = 0; k0 < K; k0 += 16) {
#pragma unroll
        for (int l = 0; l < 2; l++) {
            const int row = lr + l * 64;
            float4 va = *(const float4*)(A + (size_t)(bm + row) * K + k0 + lg * 4);
            As[lg * 4 + 0][row] = va.x;
            As[lg * 4 + 1][row] = va.y;
            As[lg * 4 + 2][row] = va.z;
            As[lg * 4 + 3][row] = va.w;
            float4 vb = *(const float4*)(B + (size_t)(bn + row) * K + k0 + lg * 4);
            Bs[lg * 4 + 0][row] = vb.x;
            Bs[lg * 4 + 1][row] = vb.y;
            Bs[lg * 4 + 2][row] = vb.z;
            Bs[lg * 4 + 3][row] = vb.w;
        }
        __syncthreads();

#pragma unroll
        for (int kk = 0; kk < 16; kk++) {
            float a[8], b[8];
            *(float4*)&a[0] = *(const float4*)&As[kk][ty * 8];
            *(float4*)&a[4] = *(const float4*)&As[kk][ty * 8 + 4];
            *(float4*)&b[0] = *(const float4*)&Bs[kk][tx * 8];
            *(float4*)&b[4] = *(const float4*)&Bs[kk][tx * 8 + 4];
#pragma unroll
            for (int i = 0; i < 8; i++)
#pragma unroll
                for (int j = 0; j < 8; j++) acc[i][j] += a[i] * b[j];
        }
        __syncthreads();
    }

#pragma unroll
    for (int i = 0; i < 8; i++) {
        float* c = C + (size_t)(bm + ty * 8 + i) * N + bn + tx * 8;
        *(float4*)c       = make_float4(acc[i][0], acc[i][1], acc[i][2], acc[i][3]);
        *(float4*)(c + 4) = make_float4(acc[i][4], acc[i][5], acc[i][6], acc[i][7]);
    }
}

// =======================================================================
// Row-wise softmax over T_DIM columns, in place. One block (256 thr) per row.
// Each thread holds 16 elements in registers (4 x float4).
// =======================================================================
__global__ __launch_bounds__(256)
void softmax_rows() {
    const int row = blockIdx.x;
    float* p = g_P + (size_t)row * T_DIM;
    const int t = threadIdx.x;

    float4 v[4];
    float mx = -1e30f;
#pragma unroll
    for (int i = 0; i < 4; i++) {
        v[i] = ((const float4*)p)[t + i * 256];
        mx = fmaxf(mx, fmaxf(fmaxf(v[i].x, v[i].y), fmaxf(v[i].z, v[i].w)));
    }

    __shared__ float redmax[8];
    __shared__ float redsum[8];
#pragma unroll
    for (int o = 16; o > 0; o >>= 1)
        mx = fmaxf(mx, __shfl_xor_sync(0xFFFFFFFFu, mx, o));
    if ((t & 31) == 0) redmax[t >> 5] = mx;
    __syncthreads();
    float bmax = redmax[0];
#pragma unroll
    for (int i = 1; i < 8; i++) bmax = fmaxf(bmax, redmax[i]);

    float sum = 0.f;
#pragma unroll
    for (int i = 0; i < 4; i++) {
        v[i].x = __expf(v[i].x - bmax);
        v[i].y = __expf(v[i].y - bmax);
        v[i].z = __expf(v[i].z - bmax);
        v[i].w = __expf(v[i].w - bmax);
        sum += v[i].x + v[i].y + v[i].z + v[i].w;
    }
#pragma unroll
    for (int o = 16; o > 0; o >>= 1)
        sum += __shfl_xor_sync(0xFFFFFFFFu, sum, o);
    if ((t & 31) == 0) redsum[t >> 5] = sum;
    __syncthreads();
    float bsum = 0.f;
#pragma unroll
    for (int i = 0; i < 8; i++) bsum += redsum[i];
    const float inv = 1.f / bsum;

#pragma unroll
    for (int i = 0; i < 4; i++) {
        v[i].x *= inv; v[i].y *= inv; v[i].z *= inv; v[i].w *= inv;
        ((float4*)p)[t + i * 256] = v[i];
    }
}

// =======================================================================
// Pmix[q][j] = sum_s w[s] * P[q-2s][j-2s]   (terms with negative index drop out)
// =======================================================================
__global__ __launch_bounds__(256)
void pmix_kernel(const float* __restrict__ w) {
    const size_t idx = (size_t)blockIdx.x * 256 + threadIdx.x;
    const int q = (int)(idx >> 12);
    const int j = (int)(idx & (T_DIM - 1));
    float acc = 0.f;
#pragma unroll
    for (int s = 0; s < NSHIFT; s++) {
        const int rr = q - s * STEPSZ;
        const int cc = j - s * STEPSZ;
        if (rr >= 0 && cc >= 0)
            acc += __ldg(&w[s]) * g_P[(size_t)rr * T_DIM + cc];
    }
    g_Pmix[idx] = acc;
}

// =======================================================================
// out = Pmix @ V  (A: T_DIM x T_DIM, V: T_DIM x 80, out: T_DIM x 80)
// 128-row block tile, 8x5 thread tile, split-K with atomicAdd epilogue.
// =======================================================================
__global__ __launch_bounds__(256)
void gemm_pv(const float* __restrict__ V, float* __restrict__ C, int kPerSplit) {
    __shared__ float As[16][132];
    __shared__ float Bs[16][V_DIM];

    const int tid = threadIdx.x;
    const int bm = blockIdx.x * 128;
    const int kbeg = blockIdx.y * kPerSplit;
    const int kend = kbeg + kPerSplit;
    const int ty = tid >> 4;   // rows ty*8..+7
    const int tx = tid & 15;   // cols tx*5..+4

    float acc[8][5];
#pragma unroll
    for (int i = 0; i < 8; i++)
#pragma unroll
        for (int j = 0; j < 5; j++) acc[i][j] = 0.f;

    const int lr = tid >> 2;
    const int lg = tid & 3;

    for (int k0 = kbeg; k0 < kend; k0 += 16) {
#pragma unroll
        for (int l = 0; l < 2; l++) {
            const int row = lr + l * 64;
            float4 va = *(const float4*)(g_Pmix + (size_t)(bm + row) * T_DIM + k0 + lg * 4);
            As[lg * 4 + 0][row] = va.x;
            As[lg * 4 + 1][row] = va.y;
            As[lg * 4 + 2][row] = va.z;
            As[lg * 4 + 3][row] = va.w;
        }
        for (int i = tid; i < 16 * V_DIM; i += 256) {
            const int kk = i / V_DIM;
            const int c  = i % V_DIM;
            Bs[kk][c] = V[(size_t)(k0 + kk) * V_DIM + c];
        }
        __syncthreads();

#pragma unroll
        for (int kk = 0; kk < 16; kk++) {
            float a[8], b[5];
            *(float4*)&a[0] = *(const float4*)&As[kk][ty * 8];
            *(float4*)&a[4] = *(const float4*)&As[kk][ty * 8 + 4];
#pragma unroll
            for (int j = 0; j < 5; j++) b[j] = Bs[kk][tx * 5 + j];
#pragma unroll
            for (int i = 0; i < 8; i++)
#pragma unroll
                for (int j = 0; j < 5; j++) acc[i][j] += a[i] * b[j];
        }
        __syncthreads();
    }

#pragma unroll
    for (int i = 0; i < 8; i++)
#pragma unroll
        for (int j = 0; j < 5; j++)
            atomicAdd(&C[(size_t)(bm + ty * 8 + i) * V_DIM + tx * 5 + j], acc[i][j]);
}

// =======================================================================
// kernel_launch
// inputs: 0:x [4096,256] 1:x_key [4096,256] 2:x_value [4096,80]
//         3:W_qk [256,256] 4:w_shift [1,4]      output: [4096,80] f32
// =======================================================================
extern "C" void kernel_launch(void* const* d_in, const int* in_sizes, int n_in,
                              void* d_out, int out_size) {
    const float* x  = (const float*)d_in[0];
    const float* xk = (const float*)d_in[1];
    const float* xv = (const float*)d_in[2];
    const float* W  = (const float*)d_in[3];
    const float* ws = (const float*)d_in[4];
    float* out = (float*)d_out;

    float *Qh, *Kh, *P;
    cudaGetSymbolAddress((void**)&Qh, g_Qh);
    cudaGetSymbolAddress((void**)&Kh, g_Kh);
    cudaGetSymbolAddress((void**)&P,  g_P);

    // 1-2. projections: Qh = x @ W^T, Kh = x_key @ W^T   (M=4096, N=256, K=256)
    gemm_abt<<<dim3(H_DIM / 128, T_DIM / 128), 256>>>(x,  W, Qh, T_DIM, H_DIM, Q_DIM);
    gemm_abt<<<dim3(H_DIM / 128, T_DIM / 128), 256>>>(xk, W, Kh, T_DIM, H_DIM, Q_DIM);

    // 3. S = Qh @ Kh^T   (M=N=4096, K=256)
    gemm_abt<<<dim3(T_DIM / 128, T_DIM / 128), 256>>>(Qh, Kh, P, T_DIM, T_DIM, H_DIM);

    // 4. softmax rows in place
    softmax_rows<<<T_DIM, 256>>>();

    // 5. Pmix = sum_s w[s] * shift2d(P, 2s)
    pmix_kernel<<<(int)(((size_t)T_DIM * T_DIM) / 256), 256>>>(ws);

    // 6. out = Pmix @ V  (split-K=8, atomicAdd epilogue)
    cudaMemsetAsync(d_out, 0, (size_t)out_size * sizeof(float), 0);
    gemm_pv<<<dim3(T_DIM / 128, 8), 256>>>(xv, out, T_DIM / 8);
}

// round 3
// speedup vs baseline: 1.1996x; 1.1996x over previous
#include <cuda_runtime.h>
#include <cuda_bf16.h>
#include <cstdint>
#include <cstddef>

#define T_DIM 4096
#define Q_DIM 256
#define H_DIM 256
#define V_DIM 80
#define NSHIFT 4
#define STEPSZ 2

#define KTRIP (3 * H_DIM)     // 768: [hi|hi|lo] x [hi|lo|hi]

// ---------------- scratch (allocation-free: __device__ globals) ----------------
__device__ __nv_bfloat16 g_Sa[(size_t)T_DIM * KTRIP];   // 6 MB  A' for S gemm
__device__ __nv_bfloat16 g_Sb[(size_t)T_DIM * KTRIP];   // 6 MB  B' for S gemm
__device__ float g_P[(size_t)T_DIM * T_DIM];            // 64 MB : S then softmax(S)

// ============================ helpers ============================
__device__ __forceinline__ uint32_t smem_u32(const void* p) {
    uint32_t a;
    asm("{ .reg .u64 t; cvta.to.shared.u64 t, %1; cvt.u32.u64 %0, t; }" : "=r"(a) : "l"(p));
    return a;
}

__device__ __forceinline__ void ldsm_x4(uint32_t* r, uint32_t addr) {
    asm volatile("ldmatrix.sync.aligned.m8n8.x4.shared.b16 {%0,%1,%2,%3}, [%4];"
                 : "=r"(r[0]), "=r"(r[1]), "=r"(r[2]), "=r"(r[3]) : "r"(addr));
}

__device__ __forceinline__ void mma_bf16(float* c, const uint32_t* a, const uint32_t* b) {
    asm volatile(
        "mma.sync.aligned.m16n8k16.row.col.f32.bf16.bf16.f32 "
        "{%0,%1,%2,%3}, {%4,%5,%6,%7}, {%8,%9}, {%0,%1,%2,%3};"
        : "+f"(c[0]), "+f"(c[1]), "+f"(c[2]), "+f"(c[3])
        : "r"(a[0]), "r"(a[1]), "r"(a[2]), "r"(a[3]), "r"(b[0]), "r"(b[1]));
}

// =======================================================================
// Projection GEMM: C = A @ B^T (fp32 in, hi/lo bf16 tripled-K out).
// mode 0 (query):  cols [0:256)=hi [256:512)=hi [512:768)=lo
// mode 1 (key):    cols [0:256)=hi [256:512)=lo [512:768)=hi
// =======================================================================
__global__ __launch_bounds__(256, 2)
void gemm_proj(const float* __restrict__ A, const float* __restrict__ B,
               __nv_bfloat16* __restrict__ dst, int mode, int M, int N, int K) {
    __shared__ float As[16][132];
    __shared__ float Bs[16][132];

    const int tid = threadIdx.x;
    const int bm = blockIdx.y * 128;
    const int bn = blockIdx.x * 128;
    const int ty = tid >> 4;
    const int tx = tid & 15;

    float acc[8][8];
#pragma unroll
    for (int i = 0; i < 8; i++)
#pragma unroll
        for (int j = 0; j < 8; j++) acc[i][j] = 0.f;

    const int lr = tid >> 2;
    const int lg = tid & 3;

    for (int k0 = 0; k0 < K; k0 += 16) {
#pragma unroll
        for (int l = 0; l < 2; l++) {
            const int row = lr + l * 64;
            float4 va = *(const float4*)(A + (size_t)(bm + row) * K + k0 + lg * 4);
            As[lg * 4 + 0][row] = va.x;
            As[lg * 4 + 1][row] = va.y;
            As[lg * 4 + 2][row] = va.z;
            As[lg * 4 + 3][row] = va.w;
            float4 vb = *(const float4*)(B + (size_t)(bn + row) * K + k0 + lg * 4);
            Bs[lg * 4 + 0][row] = vb.x;
            Bs[lg * 4 + 1][row] = vb.y;
            Bs[lg * 4 + 2][row] = vb.z;
            Bs[lg * 4 + 3][row] = vb.w;
        }
        __syncthreads();
#pragma unroll
        for (int kk = 0; kk < 16; kk++) {
            float a[8], b[8];
            *(float4*)&a[0] = *(const float4*)&As[kk][ty * 8];
            *(float4*)&a[4] = *(const float4*)&As[kk][ty * 8 + 4];
            *(float4*)&b[0] = *(const float4*)&Bs[kk][tx * 8];
            *(float4*)&b[4] = *(const float4*)&Bs[kk][tx * 8 + 4];
#pragma unroll
            for (int i = 0; i < 8; i++)
#pragma unroll
                for (int j = 0; j < 8; j++) acc[i][j] += a[i] * b[j];
        }
        __syncthreads();
    }

#pragma unroll
    for (int i = 0; i < 8; i++) {
        const size_t rbase = (size_t)(bm + ty * 8 + i) * KTRIP;
        const int cbase = bn + tx * 8;
#pragma unroll
        for (int j = 0; j < 8; j++) {
            float v = acc[i][j];
            __nv_bfloat16 h = __float2bfloat16(v);
            __nv_bfloat16 l = __float2bfloat16(v - __bfloat162float(h));
            dst[rbase + cbase + j] = h;
            dst[rbase + 256 + cbase + j] = mode ? l : h;
            dst[rbase + 512 + cbase + j] = mode ? h : l;
        }
    }
}

// =======================================================================
// S = A' @ B'^T over K=768 bf16 via mma.sync m16n8k16 (fp32 accum).
// 128x128 CTA tile, 8 warps (2x4), 64x32 per warp. K chunked by 64 halves.
// =======================================================================
#define KC 64          // halves per smem chunk
#define AST 72         // smem row stride in halves (144 B -> conflict-free ldmatrix)

__global__ __launch_bounds__(256, 2)
void s_mma_kernel() {
    __shared__ __align__(16) __nv_bfloat16 sA[128 * AST];
    __shared__ __align__(16) __nv_bfloat16 sB[128 * AST];

    const int tid = threadIdx.x;
    const int warp = tid >> 5;
    const int lane = tid & 31;
    const int bm = blockIdx.y * 128;
    const int bn = blockIdx.x * 128;
    const int wm = (warp >> 2) * 64;    // 0 or 64
    const int wn = (warp & 3) * 32;     // 0,32,64,96

    const uint32_t sa = smem_u32(sA);
    const uint32_t sb_ = smem_u32(sB);

    float c[4][4][4];
#pragma unroll
    for (int i = 0; i < 4; i++)
#pragma unroll
        for (int j = 0; j < 4; j++)
#pragma unroll
            for (int q = 0; q < 4; q++) c[i][j][q] = 0.f;

    // ldmatrix lane -> matrix/row decomposition
    const int m_i = lane >> 3;          // which 8x8 matrix this lane addresses
    const int lrow = lane & 7;

    for (int chunk = 0; chunk < KTRIP / KC; chunk++) {
        const int kb = chunk * KC;
        // stage A,B tiles: 128 rows x 64 halves (128B/row) each
#pragma unroll
        for (int i = 0; i < 4; i++) {
            const int idx = tid + i * 256;       // 0..1023
            const int row = idx >> 3;
            const int c8 = idx & 7;              // 16B chunk within row
            *(uint4*)((char*)sA + row * (AST * 2) + c8 * 16) =
                *(const uint4*)(g_Sa + (size_t)(bm + row) * KTRIP + kb + c8 * 8);
            *(uint4*)((char*)sB + row * (AST * 2) + c8 * 16) =
                *(const uint4*)(g_Sb + (size_t)(bn + row) * KTRIP + kb + c8 * 8);
        }
        __syncthreads();

#pragma unroll
        for (int ks = 0; ks < KC / 16; ks++) {
            const int k0 = ks * 16;
            uint32_t a[4][4], b[2][4];
            // A fragments: matrices 0:(m+0,k+0) 1:(m+8,k+0) 2:(m+0,k+8) 3:(m+8,k+8)
            {
                const int moff = (m_i & 1) * 8;
                const int koff = (m_i >> 1) * 8;
#pragma unroll
                for (int mt = 0; mt < 4; mt++) {
                    const int arow = wm + mt * 16 + moff + lrow;
                    ldsm_x4(a[mt], sa + arow * (AST * 2) + (k0 + koff) * 2);
                }
            }
            // B fragments: matrices 0:(n+0,k+0) 1:(n+0,k+8) 2:(n+8,k+0) 3:(n+8,k+8)
            {
                const int noff = (m_i >> 1) * 8;
                const int koff = (m_i & 1) * 8;
#pragma unroll
                for (int np = 0; np < 2; np++) {
                    const int brow = wn + np * 16 + noff + lrow;
                    ldsm_x4(b[np], sb_ + brow * (AST * 2) + (k0 + koff) * 2);
                }
            }
#pragma unroll
            for (int mt = 0; mt < 4; mt++)
#pragma unroll
                for (int nt = 0; nt < 4; nt++)
                    mma_bf16(c[mt][nt], a[mt], &b[nt >> 1][(nt & 1) * 2]);
        }
        __syncthreads();
    }

    // epilogue: fragment -> global (float2 stores, 128B/row per warp)
    const int g = lane >> 2;
    const int tig = lane & 3;
#pragma unroll
    for (int mt = 0; mt < 4; mt++) {
        const int row0 = bm + wm + mt * 16 + g;
#pragma unroll
        for (int nt = 0; nt < 4; nt++) {
            const int col = bn + wn + nt * 8 + tig * 2;
            *(float2*)&g_P[(size_t)row0 * T_DIM + col] = make_float2(c[mt][nt][0], c[mt][nt][1]);
            *(float2*)&g_P[(size_t)(row0 + 8) * T_DIM + col] = make_float2(c[mt][nt][2], c[mt][nt][3]);
        }
    }
}

// =======================================================================
// Row softmax in place
// =======================================================================
__global__ __launch_bounds__(256)
void softmax_rows() {
    const int row = blockIdx.x;
    float* p = g_P + (size_t)row * T_DIM;
    const int t = threadIdx.x;

    float4 v[4];
    float mx = -1e30f;
#pragma unroll
    for (int i = 0; i < 4; i++) {
        v[i] = ((const float4*)p)[t + i * 256];
        mx = fmaxf(mx, fmaxf(fmaxf(v[i].x, v[i].y), fmaxf(v[i].z, v[i].w)));
    }

    __shared__ float redmax[8];
    __shared__ float redsum[8];
#pragma unroll
    for (int o = 16; o > 0; o >>= 1)
        mx = fmaxf(mx, __shfl_xor_sync(0xFFFFFFFFu, mx, o));
    if ((t & 31) == 0) redmax[t >> 5] = mx;
    __syncthreads();
    float bmax = redmax[0];
#pragma unroll
    for (int i = 1; i < 8; i++) bmax = fmaxf(bmax, redmax[i]);

    float sum = 0.f;
#pragma unroll
    for (int i = 0; i < 4; i++) {
        v[i].x = __expf(v[i].x - bmax);
        v[i].y = __expf(v[i].y - bmax);
        v[i].z = __expf(v[i].z - bmax);
        v[i].w = __expf(v[i].w - bmax);
        sum += v[i].x + v[i].y + v[i].z + v[i].w;
    }
#pragma unroll
    for (int o = 16; o > 0; o >>= 1)
        sum += __shfl_xor_sync(0xFFFFFFFFu, sum, o);
    if ((t & 31) == 0) redsum[t >> 5] = sum;
    __syncthreads();
    float bsum = 0.f;
#pragma unroll
    for (int i = 0; i < 8; i++) bsum += redsum[i];
    const float inv = 1.f / bsum;

#pragma unroll
    for (int i = 0; i < 4; i++) {
        v[i].x *= inv; v[i].y *= inv; v[i].z *= inv; v[i].w *= inv;
        ((float4*)p)[t + i * 256] = v[i];
    }
}

// =======================================================================
// out = (sum_s w[s]*shift2d(P,2s)) @ V — pmix fused into A-tile load.
// Split-K=8 with atomicAdd epilogue.
// =======================================================================
__global__ __launch_bounds__(256)
void gemm_pv(const float* __restrict__ V, const float* __restrict__ w4,
             float* __restrict__ C, int kPerSplit) {
    __shared__ float As[16][132];
    __shared__ float Bs[16][V_DIM];

    const int tid = threadIdx.x;
    const int bm = blockIdx.x * 128;
    const int kbeg = blockIdx.y * kPerSplit;
    const int kend = kbeg + kPerSplit;
    const int ty = tid >> 4;
    const int tx = tid & 15;

    float w[NSHIFT];
#pragma unroll
    for (int s = 0; s < NSHIFT; s++) w[s] = __ldg(&w4[s]);

    float acc[8][5];
#pragma unroll
    for (int i = 0; i < 8; i++)
#pragma unroll
        for (int j = 0; j < 5; j++) acc[i][j] = 0.f;

    for (int k0 = kbeg; k0 < kend; k0 += 16) {
#pragma unroll
        for (int i = 0; i < 8; i++) {
            const int idx = tid + i * 256;
            const int row = idx >> 4;
            const int kk = idx & 15;
            const int grow = bm + row;
            const int gk = k0 + kk;
            float a = 0.f;
#pragma unroll
            for (int s = 0; s < NSHIFT; s++) {
                const int rr = grow - s * STEPSZ;
                const int cc = gk - s * STEPSZ;
                if (rr >= 0 && cc >= 0)
                    a += w[s] * g_P[(size_t)rr * T_DIM + cc];
            }
            As[kk][row] = a;
        }
        for (int i = tid; i < 16 * V_DIM; i += 256) {
            const int kk = i / V_DIM;
            const int c = i % V_DIM;
            Bs[kk][c] = V[(size_t)(k0 + kk) * V_DIM + c];
        }
        __syncthreads();

#pragma unroll
        for (int kk = 0; kk < 16; kk++) {
            float a[8], b[5];
            *(float4*)&a[0] = *(const float4*)&As[kk][ty * 8];
            *(float4*)&a[4] = *(const float4*)&As[kk][ty * 8 + 4];
#pragma unroll
            for (int j = 0; j < 5; j++) b[j] = Bs[kk][tx * 5 + j];
#pragma unroll
            for (int i = 0; i < 8; i++)
#pragma unroll
                for (int j = 0; j < 5; j++) acc[i][j] += a[i] * b[j];
        }
        __syncthreads();
    }

#pragma unroll
    for (int i = 0; i < 8; i++)
#pragma unroll
        for (int j = 0; j < 5; j++)
            atomicAdd(&C[(size_t)(bm + ty * 8 + i) * V_DIM + tx * 5 + j], acc[i][j]);
}

// =======================================================================
extern "C" void kernel_launch(void* const* d_in, const int* in_sizes, int n_in,
                              void* d_out, int out_size) {
    const float* x  = (const float*)d_in[0];
    const float* xk = (const float*)d_in[1];
    const float* xv = (const float*)d_in[2];
    const float* W  = (const float*)d_in[3];
    const float* ws = (const float*)d_in[4];
    float* out = (float*)d_out;

    __nv_bfloat16 *Sa, *Sb;
    cudaGetSymbolAddress((void**)&Sa, g_Sa);
    cudaGetSymbolAddress((void**)&Sb, g_Sb);

    // 1-2. projections -> tripled-K bf16 hi/lo operands
    gemm_proj<<<dim3(H_DIM / 128, T_DIM / 128), 256>>>(x,  W, Sa, 0, T_DIM, H_DIM, Q_DIM);
    gemm_proj<<<dim3(H_DIM / 128, T_DIM / 128), 256>>>(xk, W, Sb, 1, T_DIM, H_DIM, Q_DIM);

    // 3. S = A' @ B'^T via mma.sync (single bf16 GEMM, K=768)
    s_mma_kernel<<<dim3(T_DIM / 128, T_DIM / 128), 256>>>();

    // 4. softmax rows in place
    softmax_rows<<<T_DIM, 256>>>();

    // 5-6. out = Pmix @ V with fused shift-mix (split-K=8, atomicAdd)
    cudaMemsetAsync(d_out, 0, (size_t)out_size * sizeof(float), 0);
    gemm_pv<<<dim3(T_DIM / 128, 8), 256>>>(xv, ws, out, T_DIM / 8);
}

// round 5
// speedup vs baseline: 1.6534x; 1.3782x over previous
#include <cuda_runtime.h>
#include <cuda_bf16.h>
#include <cstdint>
#include <cstddef>

#define T_DIM 4096
#define QK 256
#define V_DIM 80
#define NSHIFT 4
#define STEPSZ 2
#define KTRIP 768          // tripled K: [hi|hi|lo] x [hi|lo|hi]
#define KC 64              // halves per smem chunk
#define AST 72             // smem row stride in halves (conflict-free ldmatrix)

// ---------------- scratch (allocation-free: __device__ globals) ----------------
__device__ __nv_bfloat16 g_Ta[(size_t)T_DIM * KTRIP];   // tripled x
__device__ __nv_bfloat16 g_Tb[(size_t)T_DIM * KTRIP];   // tripled x_key
__device__ __nv_bfloat16 g_Tw[(size_t)QK * KTRIP];      // tripled W
__device__ __nv_bfloat16 g_Sa[(size_t)T_DIM * KTRIP];   // tripled q
__device__ __nv_bfloat16 g_Sb[(size_t)T_DIM * KTRIP];   // tripled k
__device__ float g_P[(size_t)T_DIM * T_DIM];            // 64 MB : S then softmax(S)

// ============================ helpers ============================
__device__ __forceinline__ uint32_t smem_u32(const void* p) {
    uint32_t a;
    asm("{ .reg .u64 t; cvta.to.shared.u64 t, %1; cvt.u32.u64 %0, t; }" : "=r"(a) : "l"(p));
    return a;
}

__device__ __forceinline__ void ldsm_x4(uint32_t* r, uint32_t addr) {
    asm volatile("ldmatrix.sync.aligned.m8n8.x4.shared.b16 {%0,%1,%2,%3}, [%4];"
                 : "=r"(r[0]), "=r"(r[1]), "=r"(r[2]), "=r"(r[3]) : "r"(addr));
}

__device__ __forceinline__ void mma_bf16(float* c, const uint32_t* a, const uint32_t* b) {
    asm volatile(
        "mma.sync.aligned.m16n8k16.row.col.f32.bf16.bf16.f32 "
        "{%0,%1,%2,%3}, {%4,%5,%6,%7}, {%8,%9}, {%0,%1,%2,%3};"
        : "+f"(c[0]), "+f"(c[1]), "+f"(c[2]), "+f"(c[3])
        : "r"(a[0]), "r"(a[1]), "r"(a[2]), "r"(a[3]), "r"(b[0]), "r"(b[1]));
}

__device__ __forceinline__ void cpa16(uint32_t dst, const void* src) {
    asm volatile("cp.async.cg.shared.global [%0], [%1], 16;" :: "r"(dst), "l"(src) : "memory");
}
#define CP_COMMIT() asm volatile("cp.async.commit_group;" ::: "memory")
#define CP_WAIT1()  asm volatile("cp.async.wait_group 1;" ::: "memory")

// hi/lo split store in tripled layout. mode 0 -> [hi|hi|lo], mode 1 -> [hi|lo|hi]
__device__ __forceinline__ void store_trip(__nv_bfloat16* row_base, int col, float v, int mode) {
    __nv_bfloat16 h = __float2bfloat16(v);
    __nv_bfloat16 l = __float2bfloat16(v - __bfloat162float(h));
    row_base[col] = h;
    row_base[256 + col] = mode ? l : h;
    row_base[512 + col] = mode ? h : l;
}

// =======================================================================
// Elementwise input tripling: fp32 [M x 256] -> bf16 [M x 768]
// =======================================================================
__global__ __launch_bounds__(256)
void trip_kernel(const float* __restrict__ in, __nv_bfloat16* __restrict__ out, int mode) {
    const int idx = blockIdx.x * 256 + threadIdx.x;
    const int row = idx >> 8;
    const int col = idx & 255;
    store_trip(out + (size_t)row * KTRIP, col, in[idx], mode);
}

// =======================================================================
// Unified bf16 mma GEMM: C = A(Mx768) @ B(Nx768)^T, fp32 accum.
// 128x128 CTA tile, 8 warps (2x4), 64x32 per warp, 2-stage cp.async pipeline.
// emode 0: C -> g_P (fp32).  emode 1: tripled split -> g_Sa (mode0).
// emode 2: tripled split -> g_Sb (mode1).
// =======================================================================
#define TILE_BYTES (128 * AST * 2)      // 18432
#define STAGE_BYTES (2 * TILE_BYTES)    // A + B per stage
#define MMA_SMEM (2 * STAGE_BYTES)      // 73728

__global__ __launch_bounds__(256)
void mma_abt_kernel(const __nv_bfloat16* __restrict__ A,
                    const __nv_bfloat16* __restrict__ B, int emode) {
    extern __shared__ char smem[];
    const uint32_t smbase = smem_u32(smem);
    const int tid = threadIdx.x;
    const int warp = tid >> 5;
    const int lane = tid & 31;
    const int bm = blockIdx.y * 128;
    const int bn = blockIdx.x * 128;
    const int wm = (warp >> 2) * 64;
    const int wn = (warp & 3) * 32;
    const int m_i = lane >> 3;
    const int lrow = lane & 7;

    float c[4][4][4];
#pragma unroll
    for (int i = 0; i < 4; i++)
#pragma unroll
        for (int j = 0; j < 4; j++)
#pragma unroll
            for (int q = 0; q < 4; q++) c[i][j][q] = 0.f;

    // prologue: issue chunk 0
    {
        const uint32_t base = smbase;
#pragma unroll
        for (int i = 0; i < 4; i++) {
            const int idx = tid + i * 256;
            const int row = idx >> 3;
            const int c8 = idx & 7;
            const uint32_t off = (uint32_t)row * (AST * 2) + c8 * 16;
            cpa16(base + off, A + (size_t)(bm + row) * KTRIP + c8 * 8);
            cpa16(base + TILE_BYTES + off, B + (size_t)(bn + row) * KTRIP + c8 * 8);
        }
        CP_COMMIT();
    }

    for (int chunk = 0; chunk < KTRIP / KC; chunk++) {
        if (chunk + 1 < KTRIP / KC) {
            const int kb = (chunk + 1) * KC;
            const uint32_t base = smbase + ((chunk + 1) & 1) * STAGE_BYTES;
#pragma unroll
            for (int i = 0; i < 4; i++) {
                const int idx = tid + i * 256;
                const int row = idx >> 3;
                const int c8 = idx & 7;
                const uint32_t off = (uint32_t)row * (AST * 2) + c8 * 16;
                cpa16(base + off, A + (size_t)(bm + row) * KTRIP + kb + c8 * 8);
                cpa16(base + TILE_BYTES + off, B + (size_t)(bn + row) * KTRIP + kb + c8 * 8);
            }
        }
        CP_COMMIT();
        CP_WAIT1();
        __syncthreads();

        const uint32_t sa = smbase + (chunk & 1) * STAGE_BYTES;
        const uint32_t sb = sa + TILE_BYTES;
#pragma unroll
        for (int ks = 0; ks < KC / 16; ks++) {
            const int k0 = ks * 16;
            uint32_t a[4][4], b[2][4];
            {
                const int moff = (m_i & 1) * 8;
                const int koff = (m_i >> 1) * 8;
#pragma unroll
                for (int mt = 0; mt < 4; mt++) {
                    const int arow = wm + mt * 16 + moff + lrow;
                    ldsm_x4(a[mt], sa + arow * (AST * 2) + (k0 + koff) * 2);
                }
            }
            {
                const int noff = (m_i >> 1) * 8;
                const int koff = (m_i & 1) * 8;
#pragma unroll
                for (int np = 0; np < 2; np++) {
                    const int brow = wn + np * 16 + noff + lrow;
                    ldsm_x4(b[np], sb + brow * (AST * 2) + (k0 + koff) * 2);
                }
            }
#pragma unroll
            for (int mt = 0; mt < 4; mt++)
#pragma unroll
                for (int nt = 0; nt < 4; nt++)
                    mma_bf16(c[mt][nt], a[mt], &b[nt >> 1][(nt & 1) * 2]);
        }
        __syncthreads();
    }

    // epilogue
    const int g = lane >> 2;
    const int tig = lane & 3;
    if (emode == 0) {
#pragma unroll
        for (int mt = 0; mt < 4; mt++) {
            const int row0 = bm + wm + mt * 16 + g;
#pragma unroll
            for (int nt = 0; nt < 4; nt++) {
                const int col = bn + wn + nt * 8 + tig * 2;
                *(float2*)&g_P[(size_t)row0 * T_DIM + col] =
                    make_float2(c[mt][nt][0], c[mt][nt][1]);
                *(float2*)&g_P[(size_t)(row0 + 8) * T_DIM + col] =
                    make_float2(c[mt][nt][2], c[mt][nt][3]);
            }
        }
    } else {
        __nv_bfloat16* dst = (emode == 1) ? g_Sa : g_Sb;
        const int mode = (emode == 1) ? 0 : 1;
#pragma unroll
        for (int mt = 0; mt < 4; mt++) {
            const int row0 = bm + wm + mt * 16 + g;
#pragma unroll
            for (int nt = 0; nt < 4; nt++) {
                const int col = bn + wn + nt * 8 + tig * 2;
#pragma unroll
                for (int half = 0; half < 2; half++) {
                    __nv_bfloat16* rb = dst + (size_t)(row0 + half * 8) * KTRIP;
                    store_trip(rb, col, c[mt][nt][half * 2], mode);
                    store_trip(rb, col + 1, c[mt][nt][half * 2 + 1], mode);
                }
            }
        }
    }
}

// =======================================================================
// Row softmax in place
// =======================================================================
__global__ __launch_bounds__(256)
void softmax_rows() {
    const int row = blockIdx.x;
    float* p = g_P + (size_t)row * T_DIM;
    const int t = threadIdx.x;

    float4 v[4];
    float mx = -1e30f;
#pragma unroll
    for (int i = 0; i < 4; i++) {
        v[i] = ((const float4*)p)[t + i * 256];
        mx = fmaxf(mx, fmaxf(fmaxf(v[i].x, v[i].y), fmaxf(v[i].z, v[i].w)));
    }

    __shared__ float redmax[8];
    __shared__ float redsum[8];
#pragma unroll
    for (int o = 16; o > 0; o >>= 1)
        mx = fmaxf(mx, __shfl_xor_sync(0xFFFFFFFFu, mx, o));
    if ((t & 31) == 0) redmax[t >> 5] = mx;
    __syncthreads();
    float bmax = redmax[0];
#pragma unroll
    for (int i = 1; i < 8; i++) bmax = fmaxf(bmax, redmax[i]);

    float sum = 0.f;
#pragma unroll
    for (int i = 0; i < 4; i++) {
        v[i].x = __expf(v[i].x - bmax);
        v[i].y = __expf(v[i].y - bmax);
        v[i].z = __expf(v[i].z - bmax);
        v[i].w = __expf(v[i].w - bmax);
        sum += v[i].x + v[i].y + v[i].z + v[i].w;
    }
#pragma unroll
    for (int o = 16; o > 0; o >>= 1)
        sum += __shfl_xor_sync(0xFFFFFFFFu, sum, o);
    if ((t & 31) == 0) redsum[t >> 5] = sum;
    __syncthreads();
    float bsum = 0.f;
#pragma unroll
    for (int i = 0; i < 8; i++) bsum += redsum[i];
    const float inv = 1.f / bsum;

#pragma unroll
    for (int i = 0; i < 4; i++) {
        v[i].x *= inv; v[i].y *= inv; v[i].z *= inv; v[i].w *= inv;
        ((float4*)p)[t + i * 256] = v[i];
    }
}

// =======================================================================
// PV: out = (sum_s w[s]*shift2d(P,2s)) @ V via bf16-split mma (3 combos).
// CTA: 128 rows x 96 cols (N=80 padded). 8 warps: 4 in M (32 rows) x 2 in N (48).
// K chunk 64. Pmix computed fp32 from 4 shifted P reads, split to hi/lo smem.
// Split-K=8 with atomicAdd fp32 epilogue.
// =======================================================================
#define PV_NP 96
#define PV_A_BYTES (128 * AST * 2)    // 18432
#define PV_B_BYTES (PV_NP * AST * 2)  // 13824
#define PV_SMEM (2 * PV_A_BYTES + 2 * PV_B_BYTES)  // 64512

__global__ __launch_bounds__(256)
void pv_mma_kernel(const float* __restrict__ V, const float* __restrict__ w4,
                   float* __restrict__ C, int kPerSplit) {
    extern __shared__ char smem[];
    __nv_bfloat16* sAhi = (__nv_bfloat16*)smem;
    __nv_bfloat16* sAlo = (__nv_bfloat16*)(smem + PV_A_BYTES);
    __nv_bfloat16* sBhi = (__nv_bfloat16*)(smem + 2 * PV_A_BYTES);
    __nv_bfloat16* sBlo = (__nv_bfloat16*)(smem + 2 * PV_A_BYTES + PV_B_BYTES);
    const uint32_t uAhi = smem_u32(sAhi);
    const uint32_t uAlo = smem_u32(sAlo);
    const uint32_t uBhi = smem_u32(sBhi);
    const uint32_t uBlo = smem_u32(sBlo);

    const int tid = threadIdx.x;
    const int warp = tid >> 5;
    const int lane = tid & 31;
    const int bm = blockIdx.x * 128;
    const int kbeg = blockIdx.y * kPerSplit;
    const int wm = (warp >> 1) * 32;   // 0,32,64,96
    const int wn = (warp & 1) * 48;    // 0,48
    const int m_i = lane >> 3;
    const int lrow = lane & 7;

    float w[NSHIFT];
#pragma unroll
    for (int s = 0; s < NSHIFT; s++) w[s] = __ldg(&w4[s]);

    // zero-pad B rows [80, 96) once (never overwritten)
    const __nv_bfloat16 z16 = __float2bfloat16(0.f);
    for (int i = tid; i < (PV_NP - V_DIM) * KC; i += 256) {
        const int n = V_DIM + (i >> 6);
        const int kk = i & 63;
        sBhi[n * AST + kk] = z16;
        sBlo[n * AST + kk] = z16;
    }

    float c[2][6][4];
#pragma unroll
    for (int i = 0; i < 2; i++)
#pragma unroll
        for (int j = 0; j < 6; j++)
#pragma unroll
            for (int q = 0; q < 4; q++) c[i][j][q] = 0.f;

    for (int chunk = 0; chunk < kPerSplit / KC; chunk++) {
        const int k0 = kbeg + chunk * KC;
        __syncthreads();   // protect smem reuse from previous compute

        // A: fused shift-mix, fp32 -> hi/lo bf16 smem. 8192 elems, 32/thread.
#pragma unroll 8
        for (int i = 0; i < 32; i++) {
            const int idx = i * 256 + tid;
            const int row = idx >> 6;
            const int col = idx & 63;
            const int grow = bm + row;
            const int gk = k0 + col;
            float a = 0.f;
#pragma unroll
            for (int s = 0; s < NSHIFT; s++) {
                const int rr = grow - s * STEPSZ;
                const int cc = gk - s * STEPSZ;
                if (rr >= 0 && cc >= 0) a += w[s] * g_P[(size_t)rr * T_DIM + cc];
            }
            __nv_bfloat16 h = __float2bfloat16(a);
            sAhi[row * AST + col] = h;
            sAlo[row * AST + col] = __float2bfloat16(a - __bfloat162float(h));
        }

        // B: V chunk [k0, k0+64) x 80, transposed + split into sB[n][k]
        for (int i = tid; i < KC * V_DIM; i += 256) {
            const int kk = i / V_DIM;
            const int n = i % V_DIM;
            float v = V[(size_t)(k0 + kk) * V_DIM + n];
            __nv_bfloat16 h = __float2bfloat16(v);
            sBhi[n * AST + kk] = h;
            sBlo[n * AST + kk] = __float2bfloat16(v - __bfloat162float(h));
        }
        __syncthreads();

#pragma unroll
        for (int ks = 0; ks < KC / 16; ks++) {
            const int k0f = ks * 16;
            uint32_t ahi[2][4], alo[2][4], bhi[3][4], blo[3][4];
            {
                const int moff = (m_i & 1) * 8;
                const int koff = (m_i >> 1) * 8;
#pragma unroll
                for (int mt = 0; mt < 2; mt++) {
                    const int arow = wm + mt * 16 + moff + lrow;
                    const uint32_t off = arow * (AST * 2) + (k0f + koff) * 2;
                    ldsm_x4(ahi[mt], uAhi + off);
                    ldsm_x4(alo[mt], uAlo + off);
                }
            }
            {
                const int noff = (m_i >> 1) * 8;
                const int koff = (m_i & 1) * 8;
#pragma unroll
                for (int np = 0; np < 3; np++) {
                    const int brow = wn + np * 16 + noff + lrow;
                    const uint32_t off = brow * (AST * 2) + (k0f + koff) * 2;
                    ldsm_x4(bhi[np], uBhi + off);
                    ldsm_x4(blo[np], uBlo + off);
                }
            }
#pragma unroll
            for (int mt = 0; mt < 2; mt++)
#pragma unroll
                for (int nt = 0; nt < 6; nt++) {
                    const uint32_t* bh = &bhi[nt >> 1][(nt & 1) * 2];
                    const uint32_t* bl = &blo[nt >> 1][(nt & 1) * 2];
                    mma_bf16(c[mt][nt], ahi[mt], bh);
                    mma_bf16(c[mt][nt], ahi[mt], bl);
                    mma_bf16(c[mt][nt], alo[mt], bh);
                }
        }
    }

    // epilogue: atomicAdd (split-K), mask padded cols
    const int g = lane >> 2;
    const int tig = lane & 3;
#pragma unroll
    for (int mt = 0; mt < 2; mt++) {
        const int row0 = bm + wm + mt * 16 + g;
#pragma unroll
        for (int nt = 0; nt < 6; nt++) {
            const int col = wn + nt * 8 + tig * 2;
            if (col < V_DIM) {
                atomicAdd(&C[(size_t)row0 * V_DIM + col],     c[mt][nt][0]);
                atomicAdd(&C[(size_t)row0 * V_DIM + col + 1], c[mt][nt][1]);
                atomicAdd(&C[(size_t)(row0 + 8) * V_DIM + col],     c[mt][nt][2]);
                atomicAdd(&C[(size_t)(row0 + 8) * V_DIM + col + 1], c[mt][nt][3]);
            }
        }
    }
}

// =======================================================================
extern "C" void kernel_launch(void* const* d_in, const int* in_sizes, int n_in,
                              void* d_out, int out_size) {
    const float* x  = (const float*)d_in[0];
    const float* xk = (const float*)d_in[1];
    const float* xv = (const float*)d_in[2];
    const float* W  = (const float*)d_in[3];
    const float* ws = (const float*)d_in[4];
    float* out = (float*)d_out;

    __nv_bfloat16 *Ta, *Tb, *Tw, *Sa, *Sb;
    cudaGetSymbolAddress((void**)&Ta, g_Ta);
    cudaGetSymbolAddress((void**)&Tb, g_Tb);
    cudaGetSymbolAddress((void**)&Tw, g_Tw);
    cudaGetSymbolAddress((void**)&Sa, g_Sa);
    cudaGetSymbolAddress((void**)&Sb, g_Sb);

    cudaFuncSetAttribute(mma_abt_kernel, cudaFuncAttributeMaxDynamicSharedMemorySize, MMA_SMEM);
    cudaFuncSetAttribute(pv_mma_kernel, cudaFuncAttributeMaxDynamicSharedMemorySize, PV_SMEM);

    // 1. split inputs into tripled hi/lo bf16
    trip_kernel<<<(T_DIM * QK) / 256, 256>>>(x,  Ta, 0);
    trip_kernel<<<(T_DIM * QK) / 256, 256>>>(xk, Tb, 0);
    trip_kernel<<<(QK * QK) / 256, 256>>>(W, Tw, 1);

    // 2. projections on tensor cores; epilogue writes tripled split operands
    mma_abt_kernel<<<dim3(QK / 128, T_DIM / 128), 256, MMA_SMEM>>>(Ta, Tw, 1);
    mma_abt_kernel<<<dim3(QK / 128, T_DIM / 128), 256, MMA_SMEM>>>(Tb, Tw, 2);

    // 3. S = q @ k^T (single bf16-split GEMM, K=768)
    mma_abt_kernel<<<dim3(T_DIM / 128, T_DIM / 128), 256, MMA_SMEM>>>(Sa, Sb, 0);

    // 4. softmax rows in place
    softmax_rows<<<T_DIM, 256>>>();

    // 5. out = Pmix @ V on tensor cores (fused shift-mix, split-K=8)
    cudaMemsetAsync(d_out, 0, (size_t)out_size * sizeof(float), 0);
    pv_mma_kernel<<<dim3(T_DIM / 128, 8), 256, PV_SMEM>>>(xv, ws, out, T_DIM / 8);
}